// round 4
// baseline (speedup 1.0000x reference)
#include <cuda_runtime.h>
#include <cuda_bf16.h>
#include <cstdint>

// Problem dims: msa [1,128,256,256] f32; left_w/right_w [256,32]; out_w [1024,128]
// out [1,256,256,128] f32.
#define S_DIM 128
#define R_DIM 256
#define M_DIM 256
#define C_DIM 32
#define CZ_DIM 128
#define RC_DIM 8192          // R*C  (GEMM1 M and N)
#define CE_DIM 1024          // C*C  (GEMM2 K)
#define RT_DIM 65536         // R*R  (GEMM2 M)

// ------------------------- device scratch (no allocs allowed) -------------------------
__device__ __nv_bfloat16 gAh[RC_DIM * S_DIM];   // left  hi  [rc][s]
__device__ __nv_bfloat16 gAl[RC_DIM * S_DIM];   // left  lo
__device__ __nv_bfloat16 gBh[RC_DIM * S_DIM];   // right hi  [te][s]
__device__ __nv_bfloat16 gBl[RC_DIM * S_DIM];   // right lo
__device__ __nv_bfloat16 gPh[(size_t)RT_DIM * CE_DIM];  // P hi [rt][ce]
__device__ __nv_bfloat16 gPl[(size_t)RT_DIM * CE_DIM];  // P lo
__device__ __nv_bfloat16 gWth[CZ_DIM * CE_DIM]; // W^T hi [z][ce]
__device__ __nv_bfloat16 gWtl[CZ_DIM * CE_DIM]; // W^T lo

// ------------------------- helpers -------------------------
__device__ __forceinline__ unsigned lds2(const unsigned short* p) {
    return *reinterpret_cast<const unsigned*>(p);
}

__device__ __forceinline__ void mma16816(float* c, const unsigned* a, const unsigned* b) {
    asm volatile(
        "mma.sync.aligned.m16n8k16.row.col.f32.bf16.bf16.f32 "
        "{%0,%1,%2,%3}, {%4,%5,%6,%7}, {%8,%9}, {%0,%1,%2,%3};\n"
        : "+f"(c[0]), "+f"(c[1]), "+f"(c[2]), "+f"(c[3])
        : "r"(a[0]), "r"(a[1]), "r"(a[2]), "r"(a[3]), "r"(b[0]), "r"(b[1]));
}

__device__ __forceinline__ void split_store(__nv_bfloat16* ph, __nv_bfloat16* pl,
                                            size_t idx, float x) {
    __nv_bfloat16 h = __float2bfloat16_rn(x);
    ph[idx] = h;
    pl[idx] = __float2bfloat16_rn(x - __bfloat162float(h));
}

// ------------------------- kernel 1: projection -------------------------
// left[s,r,c] = sum_m msa[s,r,m]*lw[m,c];  right likewise with rw.
// Write split-bf16 to gA*[ (r*32+c) * 128 + s ] and gB*.
// Grid: 256 blocks (one per r), 256 threads (8 warps). Dyn smem 64KB (weights).
__global__ __launch_bounds__(256) void proj_kernel(const float* __restrict__ msa,
                                                   const float* __restrict__ lw,
                                                   const float* __restrict__ rw) {
    extern __shared__ float sm[];
    float* slw = sm;            // [256][32]
    float* srw = sm + 8192;     // [256][32]
    const int tid = threadIdx.x;
    for (int i = tid; i < 8192; i += 256) { slw[i] = lw[i]; srw[i] = rw[i]; }
    __syncthreads();

    const int r = blockIdx.x;
    const int w = tid >> 5, lane = tid & 31;

    for (int sg = 0; sg < 4; ++sg) {
        // 4 s-values per pass: s = w + 8*(4*sg + q)
        float v[4][8];
        int svals[4];
#pragma unroll
        for (int q = 0; q < 4; ++q) {
            int s = w + 8 * (4 * sg + q);
            svals[q] = s;
            const float* row = msa + ((size_t)(s * R_DIM + r) << 8);
#pragma unroll
            for (int i = 0; i < 8; ++i) v[q][i] = row[i * 32 + lane];
        }
        float aL[4] = {0.f, 0.f, 0.f, 0.f};
        float aR[4] = {0.f, 0.f, 0.f, 0.f};
#pragma unroll
        for (int i = 0; i < 8; ++i) {
#pragma unroll 8
            for (int j = 0; j < 32; ++j) {
                int m = i * 32 + j;
                float wl = slw[m * 32 + lane];
                float wr = srw[m * 32 + lane];
#pragma unroll
                for (int q = 0; q < 4; ++q) {
                    float x = __shfl_sync(0xffffffffu, v[q][i], j);
                    aL[q] = fmaf(x, wl, aL[q]);
                    aR[q] = fmaf(x, wr, aR[q]);
                }
            }
        }
        const int rc = r * 32 + lane;   // c = lane (same index used for t,e on right)
#pragma unroll
        for (int q = 0; q < 4; ++q) {
            size_t idx = (size_t)rc * S_DIM + svals[q];
            split_store(gAh, gAl, idx, aL[q]);
            split_store(gBh, gBl, idx, aR[q]);
        }
    }
}

// ------------------------- kernel 2: W transpose + split -------------------------
__global__ __launch_bounds__(256) void wt_kernel(const float* __restrict__ ow) {
    int idx = blockIdx.x * 256 + threadIdx.x;     // idx = ce*128 + z
    if (idx < CE_DIM * CZ_DIM) {
        int z = idx & 127, ce = idx >> 7;
        float x = ow[idx];
        split_store(gWth, gWtl, (size_t)z * CE_DIM + ce, x);
    }
}

// ------------------------- kernel 3: GEMM1 -------------------------
// P[(r,c),(t,e)] = sum_s left[(r,c),s] * right[(t,e),s]
// A = gA* [8192][128], B = gB* [8192][128]. Block tile 128x128, full K=128.
// Epilogue scatters split-bf16 into gP* at [r][t][c*32+e].
#define G1_STRIDE 136   // 128 + 8 pad (272B rows: 16B-aligned, conflict-free frags)
__global__ __launch_bounds__(256) void gemm1_kernel() {
    extern __shared__ unsigned short sm16[];
    unsigned short* sAh = sm16;
    unsigned short* sAl = sAh + 128 * G1_STRIDE;
    unsigned short* sBh = sAl + 128 * G1_STRIDE;
    unsigned short* sBl = sBh + 128 * G1_STRIDE;

    const int tid = threadIdx.x;
    const int mb = blockIdx.y * 128, nb = blockIdx.x * 128;

    // load tiles: 128 rows x 128 bf16 per plane = 2048 uint4; 8 per thread.
#pragma unroll
    for (int i = 0; i < 8; ++i) {
        int idx = tid * 8 + i;
        int row = idx >> 4, c16 = idx & 15;
        const size_t gofs = (size_t)(mb + row) * S_DIM + c16 * 8;
        const size_t gofsB = (size_t)(nb + row) * S_DIM + c16 * 8;
        const int sofs = row * G1_STRIDE + c16 * 8;
        *(uint4*)(sAh + sofs) = *(const uint4*)((const __nv_bfloat16*)gAh + gofs);
        *(uint4*)(sAl + sofs) = *(const uint4*)((const __nv_bfloat16*)gAl + gofs);
        *(uint4*)(sBh + sofs) = *(const uint4*)((const __nv_bfloat16*)gBh + gofsB);
        *(uint4*)(sBl + sofs) = *(const uint4*)((const __nv_bfloat16*)gBl + gofsB);
    }
    __syncthreads();

    const int wid = tid >> 5, lane = tid & 31;
    const int wm0 = (wid & 1) * 64, wn0 = (wid >> 1) * 32;
    const int g = lane >> 2, tg2 = (lane & 3) * 2;

    float acc[4][4][4];
#pragma unroll
    for (int mi = 0; mi < 4; ++mi)
#pragma unroll
        for (int nj = 0; nj < 4; ++nj)
#pragma unroll
            for (int k = 0; k < 4; ++k) acc[mi][nj][k] = 0.f;

#pragma unroll
    for (int ks = 0; ks < 128; ks += 16) {
        unsigned ah[4][4], al[4][4], bh[4][2], bl[4][2];
#pragma unroll
        for (int mi = 0; mi < 4; ++mi) {
            int base = (wm0 + mi * 16 + g) * G1_STRIDE + ks + tg2;
            ah[mi][0] = lds2(sAh + base);
            ah[mi][1] = lds2(sAh + base + 8 * G1_STRIDE);
            ah[mi][2] = lds2(sAh + base + 8);
            ah[mi][3] = lds2(sAh + base + 8 * G1_STRIDE + 8);
            al[mi][0] = lds2(sAl + base);
            al[mi][1] = lds2(sAl + base + 8 * G1_STRIDE);
            al[mi][2] = lds2(sAl + base + 8);
            al[mi][3] = lds2(sAl + base + 8 * G1_STRIDE + 8);
        }
#pragma unroll
        for (int nj = 0; nj < 4; ++nj) {
            int base = (wn0 + nj * 8 + g) * G1_STRIDE + ks + tg2;
            bh[nj][0] = lds2(sBh + base);
            bh[nj][1] = lds2(sBh + base + 8);
            bl[nj][0] = lds2(sBl + base);
            bl[nj][1] = lds2(sBl + base + 8);
        }
#pragma unroll
        for (int mi = 0; mi < 4; ++mi)
#pragma unroll
            for (int nj = 0; nj < 4; ++nj) {
                mma16816(acc[mi][nj], ah[mi], bh[nj]);
                mma16816(acc[mi][nj], ah[mi], bl[nj]);
                mma16816(acc[mi][nj], al[mi], bh[nj]);
            }
    }

    // epilogue: scatter split-bf16 pairs into gP[(r*256+t)*1024 + c*32 + e]
#pragma unroll
    for (int mi = 0; mi < 4; ++mi) {
#pragma unroll
        for (int nj = 0; nj < 4; ++nj) {
            int n = nb + wn0 + nj * 8 + tg2;
            int t = n >> 5, e = n & 31;
#pragma unroll
            for (int half = 0; half < 2; ++half) {
                int m = mb + wm0 + mi * 16 + g + half * 8;
                int r = m >> 5, c = m & 31;
                size_t base = (((size_t)((r << 8) | t)) << 10) + (c << 5) + e;
                float x0 = acc[mi][nj][half * 2 + 0];
                float x1 = acc[mi][nj][half * 2 + 1];
                __nv_bfloat16 h0 = __float2bfloat16_rn(x0);
                __nv_bfloat16 h1 = __float2bfloat16_rn(x1);
                unsigned hp = (unsigned)__bfloat16_as_ushort(h0) |
                              ((unsigned)__bfloat16_as_ushort(h1) << 16);
                __nv_bfloat16 l0 = __float2bfloat16_rn(x0 - __bfloat162float(h0));
                __nv_bfloat16 l1 = __float2bfloat16_rn(x1 - __bfloat162float(h1));
                unsigned lp = (unsigned)__bfloat16_as_ushort(l0) |
                              ((unsigned)__bfloat16_as_ushort(l1) << 16);
                *(unsigned*)((__nv_bfloat16*)gPh + base) = hp;
                *(unsigned*)((__nv_bfloat16*)gPl + base) = lp;
            }
        }
    }
}

// ------------------------- kernel 4: GEMM2 -------------------------
// out[(r,t),z] = sum_ce P[(r,t),ce] * Wt[z][ce].  M=65536, N=128, K=1024.
// Block tile 128x128, K-chunk 64. Grid 512 blocks.
#define G2_STRIDE 72    // 64 + 8 pad (144B rows: 16B-aligned, conflict-free)
__global__ __launch_bounds__(256) void gemm2_kernel(float* __restrict__ out) {
    extern __shared__ unsigned short sm16[];
    unsigned short* sAh = sm16;
    unsigned short* sAl = sAh + 128 * G2_STRIDE;
    unsigned short* sBh = sAl + 128 * G2_STRIDE;
    unsigned short* sBl = sBh + 128 * G2_STRIDE;

    const int tid = threadIdx.x;
    const size_t mb = (size_t)blockIdx.x * 128;
    const int wid = tid >> 5, lane = tid & 31;
    const int wm0 = (wid & 1) * 64, wn0 = (wid >> 1) * 32;
    const int g = lane >> 2, tg2 = (lane & 3) * 2;

    float acc[4][4][4];
#pragma unroll
    for (int mi = 0; mi < 4; ++mi)
#pragma unroll
        for (int nj = 0; nj < 4; ++nj)
#pragma unroll
            for (int k = 0; k < 4; ++k) acc[mi][nj][k] = 0.f;

    for (int kc = 0; kc < CE_DIM; kc += 64) {
        // load: per plane 128 rows x 64 cols = 1024 uint4; 4 per thread
#pragma unroll
        for (int i = 0; i < 4; ++i) {
            int idx = tid * 4 + i;
            int row = idx >> 3, c16 = idx & 7;
            const size_t aofs = (mb + row) * CE_DIM + kc + c16 * 8;
            const size_t bofs = (size_t)row * CE_DIM + kc + c16 * 8;
            const int sofs = row * G2_STRIDE + c16 * 8;
            *(uint4*)(sAh + sofs) = *(const uint4*)((const __nv_bfloat16*)gPh + aofs);
            *(uint4*)(sAl + sofs) = *(const uint4*)((const __nv_bfloat16*)gPl + aofs);
            *(uint4*)(sBh + sofs) = *(const uint4*)((const __nv_bfloat16*)gWth + bofs);
            *(uint4*)(sBl + sofs) = *(const uint4*)((const __nv_bfloat16*)gWtl + bofs);
        }
        __syncthreads();

#pragma unroll
        for (int ks = 0; ks < 64; ks += 16) {
            unsigned ah[4][4], al[4][4], bh[4][2], bl[4][2];
#pragma unroll
            for (int mi = 0; mi < 4; ++mi) {
                int base = (wm0 + mi * 16 + g) * G2_STRIDE + ks + tg2;
                ah[mi][0] = lds2(sAh + base);
                ah[mi][1] = lds2(sAh + base + 8 * G2_STRIDE);
                ah[mi][2] = lds2(sAh + base + 8);
                ah[mi][3] = lds2(sAh + base + 8 * G2_STRIDE + 8);
                al[mi][0] = lds2(sAl + base);
                al[mi][1] = lds2(sAl + base + 8 * G2_STRIDE);
                al[mi][2] = lds2(sAl + base + 8);
                al[mi][3] = lds2(sAl + base + 8 * G2_STRIDE + 8);
            }
#pragma unroll
            for (int nj = 0; nj < 4; ++nj) {
                int base = (wn0 + nj * 8 + g) * G2_STRIDE + ks + tg2;
                bh[nj][0] = lds2(sBh + base);
                bh[nj][1] = lds2(sBh + base + 8);
                bl[nj][0] = lds2(sBl + base);
                bl[nj][1] = lds2(sBl + base + 8);
            }
#pragma unroll
            for (int mi = 0; mi < 4; ++mi)
#pragma unroll
                for (int nj = 0; nj < 4; ++nj) {
                    mma16816(acc[mi][nj], ah[mi], bh[nj]);
                    mma16816(acc[mi][nj], ah[mi], bl[nj]);
                    mma16816(acc[mi][nj], al[mi], bh[nj]);
                }
        }
        __syncthreads();
    }

    // epilogue: out[m*128 + n], coalesced float2 stores
#pragma unroll
    for (int mi = 0; mi < 4; ++mi) {
#pragma unroll
        for (int nj = 0; nj < 4; ++nj) {
            int n = wn0 + nj * 8 + tg2;
#pragma unroll
            for (int half = 0; half < 2; ++half) {
                size_t m = mb + wm0 + mi * 16 + g + half * 8;
                float2 v;
                v.x = acc[mi][nj][half * 2 + 0];
                v.y = acc[mi][nj][half * 2 + 1];
                *(float2*)(out + m * CZ_DIM + n) = v;
            }
        }
    }
}

// ------------------------- launch -------------------------
extern "C" void kernel_launch(void* const* d_in, const int* in_sizes, int n_in,
                              void* d_out, int out_size) {
    const float* msa = (const float*)d_in[0];
    const float* lw  = (const float*)d_in[1];
    const float* rw  = (const float*)d_in[2];
    const float* ow  = (const float*)d_in[3];
    float* out = (float*)d_out;

    (void)in_sizes; (void)n_in; (void)out_size;

    const int proj_smem = 2 * 8192 * (int)sizeof(float);             // 64 KB
    const int g1_smem   = 4 * 128 * G1_STRIDE * 2;                   // 139264 B
    const int g2_smem   = 4 * 128 * G2_STRIDE * 2;                   // 73728 B

    cudaFuncSetAttribute((const void*)proj_kernel,
                         cudaFuncAttributeMaxDynamicSharedMemorySize, proj_smem);
    cudaFuncSetAttribute((const void*)gemm1_kernel,
                         cudaFuncAttributeMaxDynamicSharedMemorySize, g1_smem);
    cudaFuncSetAttribute((const void*)gemm2_kernel,
                         cudaFuncAttributeMaxDynamicSharedMemorySize, g2_smem);

    proj_kernel<<<R_DIM, 256, proj_smem>>>(msa, lw, rw);
    wt_kernel<<<(CE_DIM * CZ_DIM + 255) / 256, 256>>>(ow);
    gemm1_kernel<<<dim3(64, 64), 256, g1_smem>>>();
    gemm2_kernel<<<RT_DIM / 128, 256, g2_smem>>>(out);
}

// round 5
// speedup vs baseline: 2.1282x; 2.1282x over previous
#include <cuda_runtime.h>
#include <cuda_fp16.h>
#include <cstdint>

// Problem dims: msa [1,128,256,256] f32; left_w/right_w [256,32]; out_w [1024,128]
// out [1,256,256,128] f32.
#define S_DIM 128
#define R_DIM 256
#define M_DIM 256
#define C_DIM 32
#define CZ_DIM 128
#define RC_DIM 8192          // R*C  (GEMM1 M and N)
#define CE_DIM 1024          // C*C  (GEMM2 K)
#define RT_DIM 65536         // R*R  (GEMM2 M)

// ------------------------- device scratch (no allocs allowed) -------------------------
__device__ __half gA[RC_DIM * S_DIM];                 // left  [rc][s] fp16
__device__ __half gB[RC_DIM * S_DIM];                 // right [te][s] fp16
__device__ __half gP[(size_t)RT_DIM * CE_DIM];        // P [rt][ce] fp16
__device__ __half gWt[CZ_DIM * CE_DIM];               // W^T [z][ce] fp16

// ------------------------- helpers -------------------------
__device__ __forceinline__ unsigned lds2(const unsigned short* p) {
    return *reinterpret_cast<const unsigned*>(p);
}

__device__ __forceinline__ void mma16816h(float* c, const unsigned* a, const unsigned* b) {
    asm volatile(
        "mma.sync.aligned.m16n8k16.row.col.f32.f16.f16.f32 "
        "{%0,%1,%2,%3}, {%4,%5,%6,%7}, {%8,%9}, {%0,%1,%2,%3};\n"
        : "+f"(c[0]), "+f"(c[1]), "+f"(c[2]), "+f"(c[3])
        : "r"(a[0]), "r"(a[1]), "r"(a[2]), "r"(a[3]), "r"(b[0]), "r"(b[1]));
}

__device__ __forceinline__ void cp16(void* smem, const void* g) {
    unsigned s = (unsigned)__cvta_generic_to_shared(smem);
    asm volatile("cp.async.ca.shared.global [%0], [%1], 16;\n" :: "r"(s), "l"(g));
}
#define CP_COMMIT() asm volatile("cp.async.commit_group;\n" ::: "memory")
#define CP_WAIT0()  asm volatile("cp.async.wait_group 0;\n" ::: "memory")
#define CP_WAIT1()  asm volatile("cp.async.wait_group 1;\n" ::: "memory")

// ------------------------- kernel 1: projection -------------------------
// left[s,r,c] = sum_m msa[s,r,m]*lw[m,c];  right likewise with rw.
// Writes fp16 to gA[(r*32+c)*128 + s] / gB likewise.
__global__ __launch_bounds__(256) void proj_kernel(const float* __restrict__ msa,
                                                   const float* __restrict__ lw,
                                                   const float* __restrict__ rw) {
    extern __shared__ float sm[];
    float* slw = sm;            // [256][32]
    float* srw = sm + 8192;     // [256][32]
    const int tid = threadIdx.x;
    for (int i = tid; i < 8192; i += 256) { slw[i] = lw[i]; srw[i] = rw[i]; }
    __syncthreads();

    const int r = blockIdx.x;
    const int w = tid >> 5, lane = tid & 31;

    for (int sg = 0; sg < 4; ++sg) {
        float v[4][8];
        int svals[4];
#pragma unroll
        for (int q = 0; q < 4; ++q) {
            int s = w + 8 * (4 * sg + q);
            svals[q] = s;
            const float* row = msa + ((size_t)(s * R_DIM + r) << 8);
#pragma unroll
            for (int i = 0; i < 8; ++i) v[q][i] = row[i * 32 + lane];
        }
        float aL[4] = {0.f, 0.f, 0.f, 0.f};
        float aR[4] = {0.f, 0.f, 0.f, 0.f};
#pragma unroll
        for (int i = 0; i < 8; ++i) {
#pragma unroll 8
            for (int j = 0; j < 32; ++j) {
                int m = i * 32 + j;
                float wl = slw[m * 32 + lane];
                float wr = srw[m * 32 + lane];
#pragma unroll
                for (int q = 0; q < 4; ++q) {
                    float x = __shfl_sync(0xffffffffu, v[q][i], j);
                    aL[q] = fmaf(x, wl, aL[q]);
                    aR[q] = fmaf(x, wr, aR[q]);
                }
            }
        }
        const int rc = r * 32 + lane;
#pragma unroll
        for (int q = 0; q < 4; ++q) {
            size_t idx = (size_t)rc * S_DIM + svals[q];
            gA[idx] = __float2half_rn(aL[q]);
            gB[idx] = __float2half_rn(aR[q]);
        }
    }
}

// ------------------------- kernel 2: W transpose -------------------------
__global__ __launch_bounds__(256) void wt_kernel(const float* __restrict__ ow) {
    int idx = blockIdx.x * 256 + threadIdx.x;     // idx = ce*128 + z
    if (idx < CE_DIM * CZ_DIM) {
        int z = idx & 127, ce = idx >> 7;
        gWt[(size_t)z * CE_DIM + ce] = __float2half_rn(ow[idx]);
    }
}

// ------------------------- kernel 3: GEMM1 -------------------------
// P[(r,c),(t,e)] = sum_s left[(r,c),s] * right[(t,e),s].  Block 128x128, full K=128.
// Epilogue scatters fp16 into gP at [r][t][c*32+e].
#define G1_STRIDE 136   // 128 + 8 pad (272B rows, 16B aligned, conflict-free frags)
__global__ __launch_bounds__(256) void gemm1_kernel() {
    extern __shared__ unsigned short sm16[];
    unsigned short* sA = sm16;
    unsigned short* sB = sA + 128 * G1_STRIDE;

    const int tid = threadIdx.x;
    const int mb = blockIdx.y * 128, nb = blockIdx.x * 128;

    // cp.async fill: per plane 128 rows x 128 fp16 = 2048 x 16B; 8 per thread per plane
#pragma unroll
    for (int i = 0; i < 8; ++i) {
        int idx = tid * 8 + i;
        int row = idx >> 4, c16 = idx & 15;
        const int sofs = row * G1_STRIDE + c16 * 8;
        cp16(sA + sofs, (const __half*)gA + (size_t)(mb + row) * S_DIM + c16 * 8);
        cp16(sB + sofs, (const __half*)gB + (size_t)(nb + row) * S_DIM + c16 * 8);
    }
    CP_COMMIT();
    CP_WAIT0();
    __syncthreads();

    const int wid = tid >> 5, lane = tid & 31;
    const int wm0 = (wid & 1) * 64, wn0 = (wid >> 1) * 32;
    const int g = lane >> 2, tg2 = (lane & 3) * 2;

    float acc[4][4][4];
#pragma unroll
    for (int mi = 0; mi < 4; ++mi)
#pragma unroll
        for (int nj = 0; nj < 4; ++nj)
#pragma unroll
            for (int k = 0; k < 4; ++k) acc[mi][nj][k] = 0.f;

#pragma unroll
    for (int ks = 0; ks < 128; ks += 16) {
        unsigned a[4][4], b[4][2];
#pragma unroll
        for (int mi = 0; mi < 4; ++mi) {
            int base = (wm0 + mi * 16 + g) * G1_STRIDE + ks + tg2;
            a[mi][0] = lds2(sA + base);
            a[mi][1] = lds2(sA + base + 8 * G1_STRIDE);
            a[mi][2] = lds2(sA + base + 8);
            a[mi][3] = lds2(sA + base + 8 * G1_STRIDE + 8);
        }
#pragma unroll
        for (int nj = 0; nj < 4; ++nj) {
            int base = (wn0 + nj * 8 + g) * G1_STRIDE + ks + tg2;
            b[nj][0] = lds2(sB + base);
            b[nj][1] = lds2(sB + base + 8);
        }
#pragma unroll
        for (int mi = 0; mi < 4; ++mi)
#pragma unroll
            for (int nj = 0; nj < 4; ++nj)
                mma16816h(acc[mi][nj], a[mi], b[nj]);
    }

    // epilogue: scatter fp16 pairs into gP[(r*256+t)*1024 + c*32 + e]
#pragma unroll
    for (int mi = 0; mi < 4; ++mi) {
#pragma unroll
        for (int nj = 0; nj < 4; ++nj) {
            int n = nb + wn0 + nj * 8 + tg2;
            int t = n >> 5, e = n & 31;
#pragma unroll
            for (int half = 0; half < 2; ++half) {
                int m = mb + wm0 + mi * 16 + g + half * 8;
                int r = m >> 5, c = m & 31;
                size_t base = (((size_t)((r << 8) | t)) << 10) + (c << 5) + e;
                __half h0 = __float2half_rn(acc[mi][nj][half * 2 + 0]);
                __half h1 = __float2half_rn(acc[mi][nj][half * 2 + 1]);
                unsigned hp = (unsigned)__half_as_ushort(h0) |
                              ((unsigned)__half_as_ushort(h1) << 16);
                *(unsigned*)((__half*)gP + base) = hp;
            }
        }
    }
}

// ------------------------- kernel 4: GEMM2 -------------------------
// out[(r,t),z] = sum_ce P[(r,t),ce] * Wt[z][ce]. M=65536, N=128, K=1024.
// Block 128x128, K-chunk 64, cp.async double-buffered. Grid 512 blocks.
#define G2_STRIDE 72    // 64 + 8 pad (144B rows)
#define G2_PLANE  (128 * G2_STRIDE)
__global__ __launch_bounds__(256, 2) void gemm2_kernel(float* __restrict__ out) {
    extern __shared__ unsigned short sm16[];
    // stages: [stage][A|B][128][G2_STRIDE]
    unsigned short* sbuf = sm16;

    const int tid = threadIdx.x;
    const size_t mb = (size_t)blockIdx.x * 128;
    const int wid = tid >> 5, lane = tid & 31;
    const int wm0 = (wid & 1) * 64, wn0 = (wid >> 1) * 32;
    const int g = lane >> 2, tg2 = (lane & 3) * 2;

    // issue one 64-wide K chunk into stage st
    auto issue = [&](int st, int kc) {
        unsigned short* sA = sbuf + st * 2 * G2_PLANE;
        unsigned short* sB = sA + G2_PLANE;
#pragma unroll
        for (int i = 0; i < 4; ++i) {
            int idx = tid * 4 + i;
            int row = idx >> 3, seg = idx & 7;
            const int sofs = row * G2_STRIDE + seg * 8;
            cp16(sA + sofs, (const __half*)gP + (mb + row) * CE_DIM + kc + seg * 8);
            cp16(sB + sofs, (const __half*)gWt + (size_t)row * CE_DIM + kc + seg * 8);
        }
        CP_COMMIT();
    };

    float acc[4][4][4];
#pragma unroll
    for (int mi = 0; mi < 4; ++mi)
#pragma unroll
        for (int nj = 0; nj < 4; ++nj)
#pragma unroll
            for (int k = 0; k < 4; ++k) acc[mi][nj][k] = 0.f;

    issue(0, 0);

    for (int kci = 0; kci < 16; ++kci) {
        const int cur = kci & 1;
        if (kci + 1 < 16) {
            issue(cur ^ 1, (kci + 1) * 64);
            CP_WAIT1();
        } else {
            CP_WAIT0();
        }
        __syncthreads();

        unsigned short* sA = sbuf + cur * 2 * G2_PLANE;
        unsigned short* sB = sA + G2_PLANE;
#pragma unroll
        for (int ks = 0; ks < 64; ks += 16) {
            unsigned a[4][4], b[4][2];
#pragma unroll
            for (int mi = 0; mi < 4; ++mi) {
                int base = (wm0 + mi * 16 + g) * G2_STRIDE + ks + tg2;
                a[mi][0] = lds2(sA + base);
                a[mi][1] = lds2(sA + base + 8 * G2_STRIDE);
                a[mi][2] = lds2(sA + base + 8);
                a[mi][3] = lds2(sA + base + 8 * G2_STRIDE + 8);
            }
#pragma unroll
            for (int nj = 0; nj < 4; ++nj) {
                int base = (wn0 + nj * 8 + g) * G2_STRIDE + ks + tg2;
                b[nj][0] = lds2(sB + base);
                b[nj][1] = lds2(sB + base + 8);
            }
#pragma unroll
            for (int mi = 0; mi < 4; ++mi)
#pragma unroll
                for (int nj = 0; nj < 4; ++nj)
                    mma16816h(acc[mi][nj], a[mi], b[nj]);
        }
        __syncthreads();
    }

    // epilogue: coalesced float2 stores
#pragma unroll
    for (int mi = 0; mi < 4; ++mi) {
#pragma unroll
        for (int nj = 0; nj < 4; ++nj) {
            int n = wn0 + nj * 8 + tg2;
#pragma unroll
            for (int half = 0; half < 2; ++half) {
                size_t m = mb + wm0 + mi * 16 + g + half * 8;
                float2 v;
                v.x = acc[mi][nj][half * 2 + 0];
                v.y = acc[mi][nj][half * 2 + 1];
                *(float2*)(out + m * CZ_DIM + n) = v;
            }
        }
    }
}

// ------------------------- launch -------------------------
extern "C" void kernel_launch(void* const* d_in, const int* in_sizes, int n_in,
                              void* d_out, int out_size) {
    const float* msa = (const float*)d_in[0];
    const float* lw  = (const float*)d_in[1];
    const float* rw  = (const float*)d_in[2];
    const float* ow  = (const float*)d_in[3];
    float* out = (float*)d_out;

    (void)in_sizes; (void)n_in; (void)out_size;

    const int proj_smem = 2 * 8192 * (int)sizeof(float);       // 64 KB
    const int g1_smem   = 2 * 128 * G1_STRIDE * 2;             // 69632 B
    const int g2_smem   = 2 * 2 * G2_PLANE * 2;                // 73728 B (2 stages)

    cudaFuncSetAttribute((const void*)proj_kernel,
                         cudaFuncAttributeMaxDynamicSharedMemorySize, proj_smem);
    cudaFuncSetAttribute((const void*)gemm1_kernel,
                         cudaFuncAttributeMaxDynamicSharedMemorySize, g1_smem);
    cudaFuncSetAttribute((const void*)gemm2_kernel,
                         cudaFuncAttributeMaxDynamicSharedMemorySize, g2_smem);

    proj_kernel<<<R_DIM, 256, proj_smem>>>(msa, lw, rw);
    wt_kernel<<<(CE_DIM * CZ_DIM + 255) / 256, 256>>>(ow);
    gemm1_kernel<<<dim3(64, 64), 256, g1_smem>>>();
    gemm2_kernel<<<RT_DIM / 128, 256, g2_smem>>>(out);
}